// round 5
// baseline (speedup 1.0000x reference)
#include <cuda_runtime.h>

#define Bb 16
#define Qq 64
#define KK 512
#define Dd 512
#define Hh 256

// Scratch (device globals; no allocations allowed)
__device__ float g_qh[Bb * Qq * Hh];      // 1 MB
__device__ float g_kh[Bb * KK * Hh];      // 8 MB
__device__ float g_attn[Bb * Qq * KK];    // 2 MB

__device__ __forceinline__ float tanhx(float x) {
    float y;
    asm("tanh.approx.f32 %0, %1;" : "=f"(y) : "f"(x));
    return y;
}

// ---------------------------------------------------------------------------
// Fused q-proj + k-proj GEMM. Rows [0,1024) = queries@Wq -> g_qh,
// [1024,9216) = keys@Wk -> g_kh (64-row tiles fully past valid_len skipped).
// 64x64 tile, 128 threads, 4x8 microtile, k-slice 8, double buffered.
// grid = (4, 144), block = 128.
// ---------------------------------------------------------------------------
__global__ __launch_bounds__(128) void proj_gemm(
        const float* __restrict__ queries, const float* __restrict__ keys,
        const float* __restrict__ Wq, const float* __restrict__ Wk,
        const int* __restrict__ vlens) {
    const int row0 = blockIdx.y * 64;
    const int bn   = blockIdx.x * 64;

    const float *A, *Bm;
    float* C;
    if (row0 < Bb * Qq) {
        A = queries + (long)row0 * Dd; Bm = Wq; C = g_qh + (long)row0 * Hh;
    } else {
        const int krow = row0 - Bb * Qq;
        const int b    = krow >> 9;
        if ((krow & (KK - 1)) >= vlens[b]) return;   // fully-masked tile
        A = keys + (long)krow * Dd; Bm = Wk; C = g_kh + (long)krow * Hh;
    }

    __shared__ float As[2][8][68];   // transposed A: As[k][m], padded
    __shared__ float Bs[2][8][64];

    const int tid = threadIdx.x;
    const int tx  = tid & 7, ty = tid >> 3;          // 16 rows x 8 cols of threads
    const int ar  = tid >> 1, ac = (tid & 1) << 2;   // A load: row ar, k-cols ac..ac+3
    const int br  = tid >> 4, bc = (tid & 15) << 2;  // B load: row br, cols bc..bc+3

    float4 ra, rb;
    ra = *(const float4*)(A + (long)ar * Dd + ac);
    rb = *(const float4*)(Bm + (long)br * Hh + bn + bc);
    As[0][ac + 0][ar] = ra.x; As[0][ac + 1][ar] = ra.y;
    As[0][ac + 2][ar] = ra.z; As[0][ac + 3][ar] = ra.w;
    *(float4*)&Bs[0][br][bc] = rb;
    __syncthreads();

    float acc[4][8] = {};

    const int NS = Dd / 8;    // 64 slices
    for (int s = 0; s < NS; s++) {
        const int cur = s & 1;
        if (s + 1 < NS) {
            const int k0 = (s + 1) * 8;
            ra = *(const float4*)(A + (long)ar * Dd + k0 + ac);
            rb = *(const float4*)(Bm + (long)(k0 + br) * Hh + bn + bc);
        }
        #pragma unroll
        for (int kk = 0; kk < 8; kk++) {
            float4 a  = *(const float4*)&As[cur][kk][ty * 4];
            float4 b0 = *(const float4*)&Bs[cur][kk][tx * 8];
            float4 b1 = *(const float4*)&Bs[cur][kk][tx * 8 + 4];
            float am[4] = {a.x, a.y, a.z, a.w};
            float bm8[8] = {b0.x, b0.y, b0.z, b0.w, b1.x, b1.y, b1.z, b1.w};
            #pragma unroll
            for (int i = 0; i < 4; i++)
                #pragma unroll
                for (int j = 0; j < 8; j++)
                    acc[i][j] = fmaf(am[i], bm8[j], acc[i][j]);
        }
        if (s + 1 < NS) {
            const int nb = (s + 1) & 1;
            As[nb][ac + 0][ar] = ra.x; As[nb][ac + 1][ar] = ra.y;
            As[nb][ac + 2][ar] = ra.z; As[nb][ac + 3][ar] = ra.w;
            *(float4*)&Bs[nb][br][bc] = rb;
        }
        __syncthreads();
    }

    #pragma unroll
    for (int i = 0; i < 4; i++) {
        float4 o0 = make_float4(acc[i][0], acc[i][1], acc[i][2], acc[i][3]);
        float4 o1 = make_float4(acc[i][4], acc[i][5], acc[i][6], acc[i][7]);
        float* cp = C + (long)(ty * 4 + i) * Hh + bn + tx * 8;
        *(float4*)cp       = o0;
        *(float4*)(cp + 4) = o1;
    }
}

// ---------------------------------------------------------------------------
// Fused scoring + masked softmax. 256 threads = 8 warps.
// Warp w -> q-row (q0 + (w&3)), h-half (w>>2). Stage = 32 k-rows, double
// buffered: LDG of stage s+1 issued before computing stage s (load hidden
// behind MUFU). lane = k within stage: zero shuffles in scoring.
// h-half partials combined at the end via reused swq smem.
// Dynamic smem: swq[4][256] float2 + sk[2][32][257] floats = ~74 KB.
// grid = Bb*(Qq/4) = 256, block = 256.
// ---------------------------------------------------------------------------
#define SCORE_SMEM (4 * 256 * 8 + 2 * 32 * 257 * 4)

__global__ __launch_bounds__(256) void score_softmax(
        const float* __restrict__ Wv, const int* __restrict__ vlens) {
    extern __shared__ char smem_raw[];
    float2* swq = (float2*)smem_raw;                       // [4][256]
    float*  sk  = (float*)(smem_raw + 4 * 256 * 8);        // [2][32][257]

    const int bq   = blockIdx.x;
    const int b    = bq >> 4;
    const int q0   = (bq & 15) * 4;
    const int tid  = threadIdx.x;
    const int lane = tid & 31;
    const int w    = tid >> 5;
    const int q    = w & 3;
    const int hp   = w >> 2;
    const int vl   = vlens[b];

    // fill swq (1024 float2, 4 per thread)
    {
        const float* qbase = g_qh + (long)(b * Qq + q0) * Hh;
        #pragma unroll
        for (int r = 0; r < 4; r++) {
            int idx = tid + 256 * r;
            swq[idx] = make_float2(qbase[idx], Wv[idx & 255]);
        }
    }

    const float* kbase = g_kh + (long)b * KK * Hh;
    const int nst = (vl + 31) >> 5;       // 32-row stages, 1..16

    // stage-load lambda pieces: 32x256 floats = 2048 float4, 8 per thread
    const int lk  = tid >> 5;             // wait: need k index per float4 chunk
    (void)lk;

    float4 pf[8];
    {   // prologue: load + store stage 0
        const float4* gs = (const float4*)kbase;
        #pragma unroll
        for (int r = 0; r < 8; r++) pf[r] = gs[tid + 256 * r];
        #pragma unroll
        for (int r = 0; r < 8; r++) {
            int i  = tid + 256 * r;
            int k  = i >> 6;
            int h0 = (i & 63) << 2;
            float* p = sk + k * 257 + h0;
            p[0] = pf[r].x; p[1] = pf[r].y; p[2] = pf[r].z; p[3] = pf[r].w;
        }
    }
    __syncthreads();

    float valbuf[16];
    const float4* wq4 = (const float4*)(swq + q * 256) + hp * 64;

    for (int s = 0; s < nst; s++) {
        const int cur = s & 1;
        if (s + 1 < nst) {
            const float4* gs = (const float4*)(kbase + (long)(s + 1) * 32 * Hh);
            #pragma unroll
            for (int r = 0; r < 8; r++) pf[r] = gs[tid + 256 * r];
        }
        // compute: lane = k-row in stage, 128 h values (this warp's half)
        {
            const float* skrow = sk + cur * 32 * 257 + lane * 257 + hp * 128;
            float s0 = 0.f, s1 = 0.f;
            #pragma unroll 8
            for (int hh = 0; hh < 64; hh++) {
                float4 p = wq4[hh];     // (qh[2h], Wv[2h], qh[2h+1], Wv[2h+1])
                s0 = fmaf(p.y, tanhx(p.x + skrow[2 * hh]), s0);
                s1 = fmaf(p.w, tanhx(p.z + skrow[2 * hh + 1]), s1);
            }
            valbuf[s] = s0 + s1;
        }
        if (s + 1 < nst) {
            float* bufn = sk + ((s + 1) & 1) * 32 * 257;
            #pragma unroll
            for (int r = 0; r < 8; r++) {
                int i  = tid + 256 * r;
                int k  = i >> 6;
                int h0 = (i & 63) << 2;
                float* p = bufn + k * 257 + h0;
                p[0] = pf[r].x; p[1] = pf[r].y; p[2] = pf[r].z; p[3] = pf[r].w;
            }
        }
        __syncthreads();
    }
    #pragma unroll
    for (int s2 = 0; s2 < 16; s2++) if (s2 >= nst) valbuf[s2] = 0.f;

    // combine h-halves: hp=1 warps publish partials into reused swq space
    float* spart = (float*)swq;           // [4][16][32] floats = 8 KB
    if (hp == 1) {
        #pragma unroll
        for (int i = 0; i < 16; i++)
            spart[(q * 16 + i) * 32 + lane] = valbuf[i];
    }
    __syncthreads();

    if (hp == 0) {
        // full scores for q-row q0+q: k = 32*i + lane
        float vals[16];
        float mx = -3.0e38f;
        #pragma unroll
        for (int i = 0; i < 16; i++) {
            float v = valbuf[i] + spart[(q * 16 + i) * 32 + lane];
            v = (32 * i + lane < vl) ? v : -1e6f;
            vals[i] = v;
            mx = fmaxf(mx, v);
        }
        #pragma unroll
        for (int off = 16; off; off >>= 1)
            mx = fmaxf(mx, __shfl_xor_sync(0xffffffffu, mx, off));
        float sum = 0.f;
        #pragma unroll
        for (int i = 0; i < 16; i++) {
            float e = __expf(vals[i] - mx);   // masked -> exactly 0
            vals[i] = e;
            sum += e;
        }
        #pragma unroll
        for (int off = 16; off; off >>= 1)
            sum += __shfl_xor_sync(0xffffffffu, sum, off);
        const float inv = __fdividef(1.f, sum);
        float* dst = g_attn + (long)(b * Qq + q0 + q) * KK;
        for (int i = 0; i < nst; i++)      // av reads only k < align16(vl) <= 32*nst
            dst[32 * i + lane] = vals[i] * inv;
    }
}

// ---------------------------------------------------------------------------
// out[b] = attn[b] (64x512) @ values[b] (512x512), K bounded by valid_len
// (attn exactly 0 beyond). 64x64 tile, 4x4 microtile, double-buffered.
// grid = (8, 16), block = 256.
// ---------------------------------------------------------------------------
__global__ __launch_bounds__(256) void av_gemm(
        const float* __restrict__ values, float* __restrict__ out,
        const int* __restrict__ vlens) {
    const int b  = blockIdx.y;
    const int bn = blockIdx.x * 64;
    const float* A  = g_attn + (long)b * Qq * KK;
    const float* Bm = values + (long)b * KK * Dd;
    float* C        = out + (long)b * Qq * Dd;
    const int nsl   = ((vlens[b] + 15) & ~15) >> 4;   // >= 1

    __shared__ float As[2][16][64];
    __shared__ float Bs[2][16][64];

    const int tid = threadIdx.x;
    const int tx  = tid & 15, ty = tid >> 4;
    const int ar0 = tid >> 2, akc = (tid & 3) << 2;
    const int br  = tid >> 4, bc  = (tid & 15) << 2;

    float4 ra, rb;
    ra = *(const float4*)(A + (long)ar0 * KK + akc);
    rb = *(const float4*)(Bm + (long)br * Dd + bn + bc);
    As[0][akc + 0][ar0] = ra.x; As[0][akc + 1][ar0] = ra.y;
    As[0][akc + 2][ar0] = ra.z; As[0][akc + 3][ar0] = ra.w;
    *(float4*)&Bs[0][br][bc] = rb;
    __syncthreads();

    float acc[4][4] = {};

    for (int s = 0; s < nsl; s++) {
        const int cur = s & 1;
        if (s + 1 < nsl) {
            const int k0 = (s + 1) * 16;
            ra = *(const float4*)(A + (long)ar0 * KK + k0 + akc);
            rb = *(const float4*)(Bm + (long)(k0 + br) * Dd + bn + bc);
        }
        #pragma unroll
        for (int kk = 0; kk < 16; kk++) {
            float4 aq = *(const float4*)&As[cur][kk][ty * 4];
            float4 bq = *(const float4*)&Bs[cur][kk][tx * 4];
            float a4[4] = {aq.x, aq.y, aq.z, aq.w};
            float b4[4] = {bq.x, bq.y, bq.z, bq.w};
            #pragma unroll
            for (int i = 0; i < 4; i++)
                #pragma unroll
                for (int j = 0; j < 4; j++)
                    acc[i][j] = fmaf(a4[i], b4[j], acc[i][j]);
        }
        if (s + 1 < nsl) {
            const int nb = (s + 1) & 1;
            As[nb][akc + 0][ar0] = ra.x; As[nb][akc + 1][ar0] = ra.y;
            As[nb][akc + 2][ar0] = ra.z; As[nb][akc + 3][ar0] = ra.w;
            *(float4*)&Bs[nb][br][bc] = rb;
        }
        __syncthreads();
    }
    #pragma unroll
    for (int i = 0; i < 4; i++) {
        float4 o = make_float4(acc[i][0], acc[i][1], acc[i][2], acc[i][3]);
        *(float4*)(C + (long)(ty * 4 + i) * Dd + bn + tx * 4) = o;
    }
}

extern "C" void kernel_launch(void* const* d_in, const int* in_sizes, int n_in,
                              void* d_out, int out_size) {
    const float* queries = (const float*)d_in[0];  // [16,64,512]
    const float* keys    = (const float*)d_in[1];  // [16,512,512]
    const float* values  = (const float*)d_in[2];  // [16,512,512]
    const int*   vlens   = (const int*)d_in[3];    // [16]
    const float* Wq      = (const float*)d_in[4];  // [512,256]
    const float* Wk      = (const float*)d_in[5];  // [512,256]
    const float* Wv      = (const float*)d_in[6];  // [256]
    float* out = (float*)d_out;                    // [16,64,512]

    cudaFuncSetAttribute(score_softmax,
                         cudaFuncAttributeMaxDynamicSharedMemorySize, SCORE_SMEM);

    proj_gemm<<<dim3(Hh / 64, (Bb * Qq + Bb * KK) / 64), 128>>>(
        queries, keys, Wq, Wk, vlens);
    score_softmax<<<Bb * (Qq / 4), 256, SCORE_SMEM>>>(Wv, vlens);
    av_gemm<<<dim3(Dd / 64, Bb), 256>>>(values, out, vlens);
}

// round 7
// speedup vs baseline: 1.5766x; 1.5766x over previous
#include <cuda_runtime.h>
#include <cuda_bf16.h>
#include <cstdint>

#define Bb 16
#define Qq 64
#define KK 512
#define Dd 512
#define Hh 256
#define KS 32

// Scratch (device globals; no allocations allowed)
__device__ float g_qh[Bb * Qq * Hh];      // 1 MB
__device__ float g_kh[Bb * KK * Hh];      // 8 MB
__device__ float g_attn[Bb * Qq * KK];    // 2 MB

__device__ __forceinline__ float tanhx(float x) {
    float y;
    asm("tanh.approx.f32 %0, %1;" : "=f"(y) : "f"(x));
    return y;
}

// fp32 pair -> packed bf16x2 (hi parts) + packed bf16x2 (lo residuals)
// low 16 bits of each word = first argument
__device__ __forceinline__ void cvt_split2(float a, float b, uint32_t& hi, uint32_t& lo) {
    uint32_t h;
    asm("cvt.rn.bf16x2.f32 %0, %1, %2;" : "=r"(h) : "f"(b), "f"(a));
    float ah = __uint_as_float(h << 16);
    float bh = __uint_as_float(h & 0xffff0000u);
    float al = a - ah, bl = b - bh;
    asm("cvt.rn.bf16x2.f32 %0, %1, %2;" : "=r"(lo) : "f"(bl), "f"(al));
    hi = h;
}
__device__ __forceinline__ void split1(float a, uint16_t& h, uint16_t& l) {
    uint32_t hw, lw;
    cvt_split2(a, 0.f, hw, lw);
    h = (uint16_t)(hw & 0xffff);
    l = (uint16_t)(lw & 0xffff);
}

#define MMA_BF16(d, a, b0v, b1v) \
    asm volatile("mma.sync.aligned.m16n8k16.row.col.f32.bf16.bf16.f32 " \
        "{%0,%1,%2,%3}, {%4,%5,%6,%7}, {%8,%9}, {%0,%1,%2,%3};" \
        : "+f"((d)[0]), "+f"((d)[1]), "+f"((d)[2]), "+f"((d)[3]) \
        : "r"((a)[0]), "r"((a)[1]), "r"((a)[2]), "r"((a)[3]), \
          "r"(b0v), "r"(b1v))

// smem layout (bytes): bf16 rows padded to 36 elements (72 B) => conflict-free
#define RS 72
#define AH_OFF 0
#define AL_OFF (128 * RS)                  // 9216
#define BH_OFF (2 * 128 * RS)              // 18432
#define BL_OFF (BH_OFF + 64 * RS)          // 23040
#define PROJ_SMEM (BL_OFF + 64 * RS)       // 27648

// ---------------------------------------------------------------------------
// Tensor-core proj GEMM via mma.sync bf16x3 (fp32-equivalent split).
// Rows [0,1024) = queries@Wq -> g_qh, [1024,9216) = keys@Wk -> g_kh
// (128-row key tiles fully past valid_len skipped).
// Per CTA: 128x64 tile, 4 warps, warp = 32(M)x64(N), acc in registers.
// grid = (Hh/64 = 4, 72), block = 128.
// ---------------------------------------------------------------------------
__global__ __launch_bounds__(128) void proj_mma(
        const float* __restrict__ queries, const float* __restrict__ keys,
        const float* __restrict__ Wq, const float* __restrict__ Wk,
        const int* __restrict__ vlens) {
    extern __shared__ __align__(16) char sm[];
    const int tid = threadIdx.x, lane = tid & 31, w = tid >> 5;
    const int row0 = blockIdx.y * 128, bn = blockIdx.x * 64;

    const float *Ap, *Wp;
    float* Cp;
    if (row0 < Bb * Qq) {
        Ap = queries + (long)row0 * Dd; Wp = Wq; Cp = g_qh + (long)row0 * Hh;
    } else {
        const int krow = row0 - Bb * Qq;
        const int b    = krow >> 9;
        if ((krow & (KK - 1)) >= vlens[b]) return;   // fully-masked key tile
        Ap = keys + (long)krow * Dd; Wp = Wk; Cp = g_kh + (long)krow * Hh;
    }

    const int gr = lane >> 2;            // fragment group row 0..7
    const int c2 = (lane & 3) << 1;      // fragment k-col pair base

    float acc[2][8][4] = {};

    float4 ra[8], rw[4];
    // prologue LDG: slice 0. A: 128x32 fp32 (8 f4/thr), W: 32x64 fp32 (4 f4/thr)
    #pragma unroll
    for (int r = 0; r < 8; r++) {
        int i = tid + 128 * r;
        ra[r] = *(const float4*)(Ap + (long)(i >> 3) * Dd + ((i & 7) << 2));
    }
    #pragma unroll
    for (int r = 0; r < 4; r++) {
        int i = tid + 128 * r;
        rw[r] = *(const float4*)(Wp + (long)(i >> 4) * Hh + bn + ((i & 15) << 2));
    }

    const int NS = Dd / KS;    // 16 slices
    for (int s = 0; s < NS; s++) {
        // convert + STS slice s
        #pragma unroll
        for (int r = 0; r < 8; r++) {
            int i = tid + 128 * r;
            int row = i >> 3, kc = (i & 7) << 2;
            uint32_t h0, l0, h1, l1;
            cvt_split2(ra[r].x, ra[r].y, h0, l0);
            cvt_split2(ra[r].z, ra[r].w, h1, l1);
            *(uint2*)(sm + AH_OFF + row * RS + kc * 2) = make_uint2(h0, h1);
            *(uint2*)(sm + AL_OFF + row * RS + kc * 2) = make_uint2(l0, l1);
        }
        #pragma unroll
        for (int r = 0; r < 4; r++) {
            int i = tid + 128 * r;
            int k = i >> 4, nc = (i & 15) << 2;
            float v[4] = {rw[r].x, rw[r].y, rw[r].z, rw[r].w};
            #pragma unroll
            for (int j = 0; j < 4; j++) {
                uint16_t hh, ll;
                split1(v[j], hh, ll);
                *(uint16_t*)(sm + BH_OFF + (nc + j) * RS + k * 2) = hh;
                *(uint16_t*)(sm + BL_OFF + (nc + j) * RS + k * 2) = ll;
            }
        }
        __syncthreads();

        // prefetch slice s+1 (LDG overlaps MMA below)
        if (s + 1 < NS) {
            const float* Ab = Ap + (s + 1) * KS;
            const float* Wb = Wp + (long)(s + 1) * KS * Hh;
            #pragma unroll
            for (int r = 0; r < 8; r++) {
                int i = tid + 128 * r;
                ra[r] = *(const float4*)(Ab + (long)(i >> 3) * Dd + ((i & 7) << 2));
            }
            #pragma unroll
            for (int r = 0; r < 4; r++) {
                int i = tid + 128 * r;
                rw[r] = *(const float4*)(Wb + (long)(i >> 4) * Hh + bn + ((i & 15) << 2));
            }
        }

        // compute: 2 k16 halves x (2 m-tiles x 8 n-tiles) x 3 split products
        #pragma unroll
        for (int kh = 0; kh < 2; kh++) {
            const int kb = kh * 16;
            uint32_t ah[2][4], al[2][4];
            #pragma unroll
            for (int t = 0; t < 2; t++) {
                const int mr = w * 32 + 16 * t + gr;
                const char* pA = sm + (long)mr * RS + (kb + c2) * 2;
                ah[t][0] = *(const uint32_t*)(pA + AH_OFF);
                ah[t][1] = *(const uint32_t*)(pA + AH_OFF + 8 * RS);
                ah[t][2] = *(const uint32_t*)(pA + AH_OFF + 16);
                ah[t][3] = *(const uint32_t*)(pA + AH_OFF + 8 * RS + 16);
                al[t][0] = *(const uint32_t*)(pA + AL_OFF);
                al[t][1] = *(const uint32_t*)(pA + AL_OFF + 8 * RS);
                al[t][2] = *(const uint32_t*)(pA + AL_OFF + 16);
                al[t][3] = *(const uint32_t*)(pA + AL_OFF + 8 * RS + 16);
            }
            #pragma unroll
            for (int j = 0; j < 8; j++) {
                const int nr = 8 * j + gr;
                const char* pB = sm + (long)nr * RS + (kb + c2) * 2;
                uint32_t bh0 = *(const uint32_t*)(pB + BH_OFF);
                uint32_t bh1 = *(const uint32_t*)(pB + BH_OFF + 16);
                uint32_t bl0 = *(const uint32_t*)(pB + BL_OFF);
                uint32_t bl1 = *(const uint32_t*)(pB + BL_OFF + 16);
                #pragma unroll
                for (int t = 0; t < 2; t++) {
                    MMA_BF16(acc[t][j], ah[t], bh0, bh1);
                    MMA_BF16(acc[t][j], ah[t], bl0, bl1);
                    MMA_BF16(acc[t][j], al[t], bh0, bh1);
                }
            }
        }
        __syncthreads();
    }

    // epilogue: D frag rows gr, gr+8; cols c2, c2+1 of each n-tile
    #pragma unroll
    for (int t = 0; t < 2; t++) {
        const int mr = w * 32 + 16 * t + gr;
        #pragma unroll
        for (int j = 0; j < 8; j++) {
            float* cp = Cp + (long)mr * Hh + bn + 8 * j + c2;
            *(float2*)cp            = make_float2(acc[t][j][0], acc[t][j][1]);
            *(float2*)(cp + 8 * Hh) = make_float2(acc[t][j][2], acc[t][j][3]);
        }
    }
}

// ---------------------------------------------------------------------------
// Fused scoring + masked softmax (round-4 version).
// ---------------------------------------------------------------------------
#define SCORE_SMEM (4 * 256 * 8 + 2 * 32 * 257 * 4)

__global__ __launch_bounds__(256) void score_softmax(
        const float* __restrict__ Wv, const int* __restrict__ vlens) {
    extern __shared__ char smem_raw[];
    float2* swq = (float2*)smem_raw;                       // [4][256]
    float*  sk  = (float*)(smem_raw + 4 * 256 * 8);        // [2][32][257]

    const int bq   = blockIdx.x;
    const int b    = bq >> 4;
    const int q0   = (bq & 15) * 4;
    const int tid  = threadIdx.x;
    const int lane = tid & 31;
    const int w    = tid >> 5;
    const int q    = w & 3;
    const int hp   = w >> 2;
    const int vl   = vlens[b];

    {
        const float* qbase = g_qh + (long)(b * Qq + q0) * Hh;
        #pragma unroll
        for (int r = 0; r < 4; r++) {
            int idx = tid + 256 * r;
            swq[idx] = make_float2(qbase[idx], Wv[idx & 255]);
        }
    }

    const float* kbase = g_kh + (long)b * KK * Hh;
    const int nst = (vl + 31) >> 5;

    float4 pf[8];
    {
        const float4* gs = (const float4*)kbase;
        #pragma unroll
        for (int r = 0; r < 8; r++) pf[r] = gs[tid + 256 * r];
        #pragma unroll
        for (int r = 0; r < 8; r++) {
            int i = tid + 256 * r;
            int k = i >> 6, h0 = (i & 63) << 2;
            float* p = sk + k * 257 + h0;
            p[0] = pf[r].x; p[1] = pf[r].y; p[2] = pf[r].z; p[3] = pf[r].w;
        }
    }
    __syncthreads();

    float valbuf[16];
    const float4* wq4 = (const float4*)(swq + q * 256) + hp * 64;

    for (int s = 0; s < nst; s++) {
        const int cur = s & 1;
        if (s + 1 < nst) {
            const float4* gs = (const float4*)(kbase + (long)(s + 1) * 32 * Hh);
            #pragma unroll
            for (int r = 0; r < 8; r++) pf[r] = gs[tid + 256 * r];
        }
        {
            const float* skrow = sk + cur * 32 * 257 + lane * 257 + hp * 128;
            float s0 = 0.f, s1 = 0.f;
            #pragma unroll 8
            for (int hh = 0; hh < 64; hh++) {
                float4 p = wq4[hh];
                s0 = fmaf(p.y, tanhx(p.x + skrow[2 * hh]), s0);
                s1 = fmaf(p.w, tanhx(p.z + skrow[2 * hh + 1]), s1);
            }
            valbuf[s] = s0 + s1;
        }
        if (s + 1 < nst) {
            float* bufn = sk + ((s + 1) & 1) * 32 * 257;
            #pragma unroll
            for (int r = 0; r < 8; r++) {
                int i = tid + 256 * r;
                int k = i >> 6, h0 = (i & 63) << 2;
                float* p = bufn + k * 257 + h0;
                p[0] = pf[r].x; p[1] = pf[r].y; p[2] = pf[r].z; p[3] = pf[r].w;
            }
        }
        __syncthreads();
    }
    #pragma unroll
    for (int s2 = 0; s2 < 16; s2++) if (s2 >= nst) valbuf[s2] = 0.f;

    float* spart = (float*)swq;           // reuse smem: [4][16][32]
    if (hp == 1) {
        #pragma unroll
        for (int i = 0; i < 16; i++)
            spart[(q * 16 + i) * 32 + lane] = valbuf[i];
    }
    __syncthreads();

    if (hp == 0) {
        float vals[16];
        float mx = -3.0e38f;
        #pragma unroll
        for (int i = 0; i < 16; i++) {
            float v = valbuf[i] + spart[(q * 16 + i) * 32 + lane];
            v = (32 * i + lane < vl) ? v : -1e6f;
            vals[i] = v;
            mx = fmaxf(mx, v);
        }
        #pragma unroll
        for (int off = 16; off; off >>= 1)
            mx = fmaxf(mx, __shfl_xor_sync(0xffffffffu, mx, off));
        float sum = 0.f;
        #pragma unroll
        for (int i = 0; i < 16; i++) {
            float e = __expf(vals[i] - mx);
            vals[i] = e;
            sum += e;
        }
        #pragma unroll
        for (int off = 16; off; off >>= 1)
            sum += __shfl_xor_sync(0xffffffffu, sum, off);
        const float inv = __fdividef(1.f, sum);
        float* dst = g_attn + (long)(b * Qq + q0 + q) * KK;
        for (int i = 0; i < nst; i++)
            dst[32 * i + lane] = vals[i] * inv;
    }
}

// ---------------------------------------------------------------------------
// out[b] = attn[b] @ values[b], K bounded by valid_len. (round-4 version)
// ---------------------------------------------------------------------------
__global__ __launch_bounds__(256) void av_gemm(
        const float* __restrict__ values, float* __restrict__ out,
        const int* __restrict__ vlens) {
    const int b  = blockIdx.y;
    const int bn = blockIdx.x * 64;
    const float* A  = g_attn + (long)b * Qq * KK;
    const float* Bm = values + (long)b * KK * Dd;
    float* C        = out + (long)b * Qq * Dd;
    const int nsl   = ((vlens[b] + 15) & ~15) >> 4;

    __shared__ float As[2][16][64];
    __shared__ float Bs[2][16][64];

    const int tid = threadIdx.x;
    const int tx  = tid & 15, ty = tid >> 4;
    const int ar0 = tid >> 2, akc = (tid & 3) << 2;
    const int br  = tid >> 4, bc  = (tid & 15) << 2;

    float4 ra, rb;
    ra = *(const float4*)(A + (long)ar0 * KK + akc);
    rb = *(const float4*)(Bm + (long)br * Dd + bn + bc);
    As[0][akc + 0][ar0] = ra.x; As[0][akc + 1][ar0] = ra.y;
    As[0][akc + 2][ar0] = ra.z; As[0][akc + 3][ar0] = ra.w;
    *(float4*)&Bs[0][br][bc] = rb;
    __syncthreads();

    float acc[4][4] = {};

    for (int s = 0; s < nsl; s++) {
        const int cur = s & 1;
        if (s + 1 < nsl) {
            const int k0 = (s + 1) * 16;
            ra = *(const float4*)(A + (long)ar0 * KK + k0 + akc);
            rb = *(const float4*)(Bm + (long)(k0 + br) * Dd + bn + bc);
        }
        #pragma unroll
        for (int kk = 0; kk < 16; kk++) {
            float4 aq = *(const float4*)&As[cur][kk][ty * 4];
            float4 bq = *(const float4*)&Bs[cur][kk][tx * 4];
            float a4[4] = {aq.x, aq.y, aq.z, aq.w};
            float b4[4] = {bq.x, bq.y, bq.z, bq.w};
            #pragma unroll
            for (int i = 0; i < 4; i++)
                #pragma unroll
                for (int j = 0; j < 4; j++)
                    acc[i][j] = fmaf(a4[i], b4[j], acc[i][j]);
        }
        if (s + 1 < nsl) {
            const int nb = (s + 1) & 1;
            As[nb][akc + 0][ar0] = ra.x; As[nb][akc + 1][ar0] = ra.y;
            As[nb][akc + 2][ar0] = ra.z; As[nb][akc + 3][ar0] = ra.w;
            *(float4*)&Bs[nb][br][bc] = rb;
        }
        __syncthreads();
    }
    #pragma unroll
    for (int i = 0; i < 4; i++) {
        float4 o = make_float4(acc[i][0], acc[i][1], acc[i][2], acc[i][3]);
        *(float4*)(C + (long)(ty * 4 + i) * Dd + bn + tx * 4) = o;
    }
}

extern "C" void kernel_launch(void* const* d_in, const int* in_sizes, int n_in,
                              void* d_out, int out_size) {
    const float* queries = (const float*)d_in[0];  // [16,64,512]
    const float* keys    = (const float*)d_in[1];  // [16,512,512]
    const float* values  = (const float*)d_in[2];  // [16,512,512]
    const int*   vlens   = (const int*)d_in[3];    // [16]
    const float* Wq      = (const float*)d_in[4];  // [512,256]
    const float* Wk      = (const float*)d_in[5];  // [512,256]
    const float* Wv      = (const float*)d_in[6];  // [256]
    float* out = (float*)d_out;                    // [16,64,512]

    cudaFuncSetAttribute(proj_mma,
                         cudaFuncAttributeMaxDynamicSharedMemorySize, PROJ_SMEM);
    cudaFuncSetAttribute(score_softmax,
                         cudaFuncAttributeMaxDynamicSharedMemorySize, SCORE_SMEM);

    proj_mma<<<dim3(Hh / 64, (Bb * Qq + Bb * KK) / 128), 128, PROJ_SMEM>>>(
        queries, keys, Wq, Wk, vlens);
    score_softmax<<<Bb * (Qq / 4), 256, SCORE_SMEM>>>(Wv, vlens);
    av_gemm<<<dim3(Dd / 64, Bb), 256>>>(values, out, vlens);
}

// round 8
// speedup vs baseline: 2.0415x; 1.2949x over previous
#include <cuda_runtime.h>
#include <cuda_bf16.h>
#include <cstdint>

#define Bb 16
#define Qq 64
#define KK 512
#define Dd 512
#define Hh 256
#define KS 32

// Scratch (device globals; no allocations allowed)
__device__ float g_qh[Bb * Qq * Hh];      // 1 MB
__device__ float g_kh[Bb * KK * Hh];      // 8 MB
__device__ float g_attn[Bb * Qq * KK];    // 2 MB

__device__ __forceinline__ float tanhx(float x) {
    float y;
    asm("tanh.approx.f32 %0, %1;" : "=f"(y) : "f"(x));
    return y;
}

// fp32 pair -> packed bf16x2 (hi parts) + packed bf16x2 (lo residuals)
__device__ __forceinline__ void cvt_split2(float a, float b, uint32_t& hi, uint32_t& lo) {
    uint32_t h;
    asm("cvt.rn.bf16x2.f32 %0, %1, %2;" : "=r"(h) : "f"(b), "f"(a));
    float ah = __uint_as_float(h << 16);
    float bh = __uint_as_float(h & 0xffff0000u);
    float al = a - ah, bl = b - bh;
    asm("cvt.rn.bf16x2.f32 %0, %1, %2;" : "=r"(lo) : "f"(bl), "f"(al));
    hi = h;
}
__device__ __forceinline__ void split1(float a, uint16_t& h, uint16_t& l) {
    uint32_t hw, lw;
    cvt_split2(a, 0.f, hw, lw);
    h = (uint16_t)(hw & 0xffff);
    l = (uint16_t)(lw & 0xffff);
}

#define MMA_BF16(d, a, b0v, b1v) \
    asm volatile("mma.sync.aligned.m16n8k16.row.col.f32.bf16.bf16.f32 " \
        "{%0,%1,%2,%3}, {%4,%5,%6,%7}, {%8,%9}, {%0,%1,%2,%3};" \
        : "+f"((d)[0]), "+f"((d)[1]), "+f"((d)[2]), "+f"((d)[3]) \
        : "r"((a)[0]), "r"((a)[1]), "r"((a)[2]), "r"((a)[3]), \
          "r"(b0v), "r"(b1v))

// smem layout (bytes): bf16 rows padded to 36 elements (72 B)
#define RS 72
#define AH_OFF 0
#define AL_OFF (128 * RS)
#define BH_OFF (2 * 128 * RS)
#define BL_OFF (BH_OFF + 64 * RS)
#define PROJ_SMEM (BL_OFF + 64 * RS)

// ---------------------------------------------------------------------------
// Tensor-core proj GEMM via mma.sync bf16x3 (fp32-equivalent split).
// (unchanged from round 7)
// ---------------------------------------------------------------------------
__global__ __launch_bounds__(128) void proj_mma(
        const float* __restrict__ queries, const float* __restrict__ keys,
        const float* __restrict__ Wq, const float* __restrict__ Wk,
        const int* __restrict__ vlens) {
    extern __shared__ __align__(16) char sm[];
    const int tid = threadIdx.x, lane = tid & 31, w = tid >> 5;
    const int row0 = blockIdx.y * 128, bn = blockIdx.x * 64;

    const float *Ap, *Wp;
    float* Cp;
    if (row0 < Bb * Qq) {
        Ap = queries + (long)row0 * Dd; Wp = Wq; Cp = g_qh + (long)row0 * Hh;
    } else {
        const int krow = row0 - Bb * Qq;
        const int b    = krow >> 9;
        if ((krow & (KK - 1)) >= vlens[b]) return;   // fully-masked key tile
        Ap = keys + (long)krow * Dd; Wp = Wk; Cp = g_kh + (long)krow * Hh;
    }

    const int gr = lane >> 2;
    const int c2 = (lane & 3) << 1;

    float acc[2][8][4] = {};

    float4 ra[8], rw[4];
    #pragma unroll
    for (int r = 0; r < 8; r++) {
        int i = tid + 128 * r;
        ra[r] = *(const float4*)(Ap + (long)(i >> 3) * Dd + ((i & 7) << 2));
    }
    #pragma unroll
    for (int r = 0; r < 4; r++) {
        int i = tid + 128 * r;
        rw[r] = *(const float4*)(Wp + (long)(i >> 4) * Hh + bn + ((i & 15) << 2));
    }

    const int NS = Dd / KS;    // 16 slices
    for (int s = 0; s < NS; s++) {
        #pragma unroll
        for (int r = 0; r < 8; r++) {
            int i = tid + 128 * r;
            int row = i >> 3, kc = (i & 7) << 2;
            uint32_t h0, l0, h1, l1;
            cvt_split2(ra[r].x, ra[r].y, h0, l0);
            cvt_split2(ra[r].z, ra[r].w, h1, l1);
            *(uint2*)(sm + AH_OFF + row * RS + kc * 2) = make_uint2(h0, h1);
            *(uint2*)(sm + AL_OFF + row * RS + kc * 2) = make_uint2(l0, l1);
        }
        #pragma unroll
        for (int r = 0; r < 4; r++) {
            int i = tid + 128 * r;
            int k = i >> 4, nc = (i & 15) << 2;
            float v[4] = {rw[r].x, rw[r].y, rw[r].z, rw[r].w};
            #pragma unroll
            for (int j = 0; j < 4; j++) {
                uint16_t hh, ll;
                split1(v[j], hh, ll);
                *(uint16_t*)(sm + BH_OFF + (nc + j) * RS + k * 2) = hh;
                *(uint16_t*)(sm + BL_OFF + (nc + j) * RS + k * 2) = ll;
            }
        }
        __syncthreads();

        if (s + 1 < NS) {
            const float* Ab = Ap + (s + 1) * KS;
            const float* Wb = Wp + (long)(s + 1) * KS * Hh;
            #pragma unroll
            for (int r = 0; r < 8; r++) {
                int i = tid + 128 * r;
                ra[r] = *(const float4*)(Ab + (long)(i >> 3) * Dd + ((i & 7) << 2));
            }
            #pragma unroll
            for (int r = 0; r < 4; r++) {
                int i = tid + 128 * r;
                rw[r] = *(const float4*)(Wb + (long)(i >> 4) * Hh + bn + ((i & 15) << 2));
            }
        }

        #pragma unroll
        for (int kh = 0; kh < 2; kh++) {
            const int kb = kh * 16;
            uint32_t ah[2][4], al[2][4];
            #pragma unroll
            for (int t = 0; t < 2; t++) {
                const int mr = w * 32 + 16 * t + gr;
                const char* pA = sm + (long)mr * RS + (kb + c2) * 2;
                ah[t][0] = *(const uint32_t*)(pA + AH_OFF);
                ah[t][1] = *(const uint32_t*)(pA + AH_OFF + 8 * RS);
                ah[t][2] = *(const uint32_t*)(pA + AH_OFF + 16);
                ah[t][3] = *(const uint32_t*)(pA + AH_OFF + 8 * RS + 16);
                al[t][0] = *(const uint32_t*)(pA + AL_OFF);
                al[t][1] = *(const uint32_t*)(pA + AL_OFF + 8 * RS);
                al[t][2] = *(const uint32_t*)(pA + AL_OFF + 16);
                al[t][3] = *(const uint32_t*)(pA + AL_OFF + 8 * RS + 16);
            }
            #pragma unroll
            for (int j = 0; j < 8; j++) {
                const int nr = 8 * j + gr;
                const char* pB = sm + (long)nr * RS + (kb + c2) * 2;
                uint32_t bh0 = *(const uint32_t*)(pB + BH_OFF);
                uint32_t bh1 = *(const uint32_t*)(pB + BH_OFF + 16);
                uint32_t bl0 = *(const uint32_t*)(pB + BL_OFF);
                uint32_t bl1 = *(const uint32_t*)(pB + BL_OFF + 16);
                #pragma unroll
                for (int t = 0; t < 2; t++) {
                    MMA_BF16(acc[t][j], ah[t], bh0, bh1);
                    MMA_BF16(acc[t][j], ah[t], bl0, bl1);
                    MMA_BF16(acc[t][j], al[t], bh0, bh1);
                }
            }
        }
        __syncthreads();
    }

    #pragma unroll
    for (int t = 0; t < 2; t++) {
        const int mr = w * 32 + 16 * t + gr;
        #pragma unroll
        for (int j = 0; j < 8; j++) {
            float* cp = Cp + (long)mr * Hh + bn + 8 * j + c2;
            *(float2*)cp            = make_float2(acc[t][j][0], acc[t][j][1]);
            *(float2*)(cp + 8 * Hh) = make_float2(acc[t][j][2], acc[t][j][3]);
        }
    }
}

// ---------------------------------------------------------------------------
// S1: balanced scoring pass. Block = (k-tile of 16, batch). Every active
// block does identical work: 64 q x 16 k x 256 h. Blocks past vl exit.
// 256 threads = 8 warps; warp w -> local k = {2w, 2w+1}; lane -> q, q+32.
// qh staged transposed [h][65] (per-lane conflict-free); kh tile transposed
// [h][18] with Wv folded at [h][16] (broadcast reads). Raw scores -> g_attn.
// grid = (32, 16), block = 256.
// ---------------------------------------------------------------------------
#define S1_QT 65
#define S1_KT 18
#define S1_SMEM (Hh * S1_QT * 4 + Hh * S1_KT * 4)

__global__ __launch_bounds__(256) void score_pass(
        const float* __restrict__ Wv, const int* __restrict__ vlens) {
    const int kt = blockIdx.x;            // k-tile (16 wide)
    const int b  = blockIdx.y;
    const int vl = vlens[b];
    if (kt * 16 >= vl) return;

    extern __shared__ float s1[];
    float* qt = s1;                        // [256][65]
    float* ktl = s1 + Hh * S1_QT;          // [256][18], [h][16] = Wv[h]

    const int tid  = threadIdx.x;
    const int lane = tid & 31;
    const int w    = tid >> 5;

    // stage qh transposed: 4096 float4, 16/thread (coalesced LDG, scalar STS)
    {
        const float4* src = (const float4*)(g_qh + (long)b * Qq * Hh);
        #pragma unroll
        for (int r = 0; r < 16; r++) {
            int i = tid + 256 * r;
            int q = i >> 6, h0 = (i & 63) << 2;
            float4 v = src[i];
            qt[(h0 + 0) * S1_QT + q] = v.x;
            qt[(h0 + 1) * S1_QT + q] = v.y;
            qt[(h0 + 2) * S1_QT + q] = v.z;
            qt[(h0 + 3) * S1_QT + q] = v.w;
        }
    }
    // stage kh tile transposed: 1024 float4, 4/thread
    {
        const float4* src = (const float4*)(g_kh + ((long)b * KK + kt * 16) * Hh);
        #pragma unroll
        for (int r = 0; r < 4; r++) {
            int i = tid + 256 * r;
            int k = i >> 6, h0 = (i & 63) << 2;
            float4 v = src[i];
            ktl[(h0 + 0) * S1_KT + k] = v.x;
            ktl[(h0 + 1) * S1_KT + k] = v.y;
            ktl[(h0 + 2) * S1_KT + k] = v.z;
            ktl[(h0 + 3) * S1_KT + k] = v.w;
        }
    }
    ktl[tid * S1_KT + 16] = Wv[tid];       // Wv folded, one per h
    __syncthreads();

    float a00 = 0.f, a01 = 0.f, a10 = 0.f, a11 = 0.f;
    #pragma unroll 4
    for (int h = 0; h < Hh; h++) {
        const float* kr = ktl + h * S1_KT;
        float2 kv = *(const float2*)(kr + 2 * w);   // broadcast LDS.64
        float  wv = kr[16];                          // broadcast
        float  qa = qt[h * S1_QT + lane];
        float  qb = qt[h * S1_QT + lane + 32];
        a00 = fmaf(wv, tanhx(qa + kv.x), a00);
        a01 = fmaf(wv, tanhx(qa + kv.y), a01);
        a10 = fmaf(wv, tanhx(qb + kv.x), a10);
        a11 = fmaf(wv, tanhx(qb + kv.y), a11);
    }

    float* d0 = g_attn + ((long)b * Qq + lane) * KK + kt * 16 + 2 * w;
    *(float2*)d0              = make_float2(a00, a01);
    *(float2*)(d0 + 32 * KK)  = make_float2(a10, a11);
}

// ---------------------------------------------------------------------------
// S2: masked softmax over g_attn rows, in place. Warp per q-row.
// Writes exact 0 for k >= vl (preserves av's vl-bounded K loop).
// grid = Bb*16 = 256, block = 128.
// ---------------------------------------------------------------------------
__global__ __launch_bounds__(128) void softmax_k(const int* __restrict__ vlens) {
    const int b    = blockIdx.x >> 4;
    const int q0   = (blockIdx.x & 15) * 4;
    const int lane = threadIdx.x & 31;
    const int w    = threadIdx.x >> 5;
    const int vl   = vlens[b];

    float* row = g_attn + ((long)b * Qq + q0 + w) * KK;

    float vals[16];
    float mx = -3.0e38f;
    #pragma unroll
    for (int i = 0; i < 16; i++) {
        int k = 32 * i + lane;
        float v = (k < vl) ? row[k] : -1e6f;
        vals[i] = v;
        mx = fmaxf(mx, v);
    }
    #pragma unroll
    for (int off = 16; off; off >>= 1)
        mx = fmaxf(mx, __shfl_xor_sync(0xffffffffu, mx, off));
    float sum = 0.f;
    #pragma unroll
    for (int i = 0; i < 16; i++) {
        float e = __expf(vals[i] - mx);   // masked -> exactly 0
        vals[i] = e;
        sum += e;
    }
    #pragma unroll
    for (int off = 16; off; off >>= 1)
        sum += __shfl_xor_sync(0xffffffffu, sum, off);
    const float inv = __fdividef(1.f, sum);
    #pragma unroll
    for (int i = 0; i < 16; i++)
        row[32 * i + lane] = vals[i] * inv;
}

// ---------------------------------------------------------------------------
// out[b] = attn[b] @ values[b], K bounded by valid_len. (unchanged)
// ---------------------------------------------------------------------------
__global__ __launch_bounds__(256) void av_gemm(
        const float* __restrict__ values, float* __restrict__ out,
        const int* __restrict__ vlens) {
    const int b  = blockIdx.y;
    const int bn = blockIdx.x * 64;
    const float* A  = g_attn + (long)b * Qq * KK;
    const float* Bm = values + (long)b * KK * Dd;
    float* C        = out + (long)b * Qq * Dd;
    const int nsl   = ((vlens[b] + 15) & ~15) >> 4;

    __shared__ float As[2][16][64];
    __shared__ float Bs[2][16][64];

    const int tid = threadIdx.x;
    const int tx  = tid & 15, ty = tid >> 4;
    const int ar0 = tid >> 2, akc = (tid & 3) << 2;
    const int br  = tid >> 4, bc  = (tid & 15) << 2;

    float4 ra, rb;
    ra = *(const float4*)(A + (long)ar0 * KK + akc);
    rb = *(const float4*)(Bm + (long)br * Dd + bn + bc);
    As[0][akc + 0][ar0] = ra.x; As[0][akc + 1][ar0] = ra.y;
    As[0][akc + 2][ar0] = ra.z; As[0][akc + 3][ar0] = ra.w;
    *(float4*)&Bs[0][br][bc] = rb;
    __syncthreads();

    float acc[4][4] = {};

    for (int s = 0; s < nsl; s++) {
        const int cur = s & 1;
        if (s + 1 < nsl) {
            const int k0 = (s + 1) * 16;
            ra = *(const float4*)(A + (long)ar0 * KK + k0 + akc);
            rb = *(const float4*)(Bm + (long)(k0 + br) * Dd + bn + bc);
        }
        #pragma unroll
        for (int kk = 0; kk < 16; kk++) {
            float4 aq = *(const float4*)&As[cur][kk][ty * 4];
            float4 bq = *(const float4*)&Bs[cur][kk][tx * 4];
            float a4[4] = {aq.x, aq.y, aq.z, aq.w};
            float b4[4] = {bq.x, bq.y, bq.z, bq.w};
            #pragma unroll
            for (int i = 0; i < 4; i++)
                #pragma unroll
                for (int j = 0; j < 4; j++)
                    acc[i][j] = fmaf(a4[i], b4[j], acc[i][j]);
        }
        if (s + 1 < nsl) {
            const int nb = (s + 1) & 1;
            As[nb][akc + 0][ar0] = ra.x; As[nb][akc + 1][ar0] = ra.y;
            As[nb][akc + 2][ar0] = ra.z; As[nb][akc + 3][ar0] = ra.w;
            *(float4*)&Bs[nb][br][bc] = rb;
        }
        __syncthreads();
    }
    #pragma unroll
    for (int i = 0; i < 4; i++) {
        float4 o = make_float4(acc[i][0], acc[i][1], acc[i][2], acc[i][3]);
        *(float4*)(C + (long)(ty * 4 + i) * Dd + bn + tx * 4) = o;
    }
}

extern "C" void kernel_launch(void* const* d_in, const int* in_sizes, int n_in,
                              void* d_out, int out_size) {
    const float* queries = (const float*)d_in[0];  // [16,64,512]
    const float* keys    = (const float*)d_in[1];  // [16,512,512]
    const float* values  = (const float*)d_in[2];  // [16,512,512]
    const int*   vlens   = (const int*)d_in[3];    // [16]
    const float* Wq      = (const float*)d_in[4];  // [512,256]
    const float* Wk      = (const float*)d_in[5];  // [512,256]
    const float* Wv      = (const float*)d_in[6];  // [256]
    float* out = (float*)d_out;                    // [16,64,512]

    cudaFuncSetAttribute(proj_mma,
                         cudaFuncAttributeMaxDynamicSharedMemorySize, PROJ_SMEM);
    cudaFuncSetAttribute(score_pass,
                         cudaFuncAttributeMaxDynamicSharedMemorySize, S1_SMEM);

    proj_mma<<<dim3(Hh / 64, (Bb * Qq + Bb * KK) / 128), 128, PROJ_SMEM>>>(
        queries, keys, Wq, Wk, vlens);
    score_pass<<<dim3(KK / 16, Bb), 256, S1_SMEM>>>(Wv, vlens);
    softmax_k<<<Bb * 16, 128>>>(vlens);
    av_gemm<<<dim3(Dd / 64, Bb), 256>>>(values, out, vlens);
}

// round 9
// speedup vs baseline: 2.0719x; 1.0149x over previous
#include <cuda_runtime.h>
#include <cuda_bf16.h>
#include <cstdint>

#define Bb 16
#define Qq 64
#define KK 512
#define Dd 512
#define Hh 256
#define KS 32

// Scratch (device globals; no allocations allowed)
__device__ float g_qh[Bb * Qq * Hh];      // 1 MB
__device__ float g_kh[Bb * KK * Hh];      // 8 MB
__device__ float g_attn[Bb * Qq * KK];    // 2 MB

__device__ __forceinline__ float tanhx(float x) {
    float y;
    asm("tanh.approx.f32 %0, %1;" : "=f"(y) : "f"(x));
    return y;
}

// fp32 pair -> packed bf16x2 (hi parts) + packed bf16x2 (lo residuals)
__device__ __forceinline__ void cvt_split2(float a, float b, uint32_t& hi, uint32_t& lo) {
    uint32_t h;
    asm("cvt.rn.bf16x2.f32 %0, %1, %2;" : "=r"(h) : "f"(b), "f"(a));
    float ah = __uint_as_float(h << 16);
    float bh = __uint_as_float(h & 0xffff0000u);
    float al = a - ah, bl = b - bh;
    asm("cvt.rn.bf16x2.f32 %0, %1, %2;" : "=r"(lo) : "f"(bl), "f"(al));
    hi = h;
}
__device__ __forceinline__ void split1(float a, uint16_t& h, uint16_t& l) {
    uint32_t hw, lw;
    cvt_split2(a, 0.f, hw, lw);
    h = (uint16_t)(hw & 0xffff);
    l = (uint16_t)(lw & 0xffff);
}

#define MMA_BF16(d, a, b0v, b1v) \
    asm volatile("mma.sync.aligned.m16n8k16.row.col.f32.bf16.bf16.f32 " \
        "{%0,%1,%2,%3}, {%4,%5,%6,%7}, {%8,%9}, {%0,%1,%2,%3};" \
        : "+f"((d)[0]), "+f"((d)[1]), "+f"((d)[2]), "+f"((d)[3]) \
        : "r"((a)[0]), "r"((a)[1]), "r"((a)[2]), "r"((a)[3]), \
          "r"(b0v), "r"(b1v))

// proj smem layout (bytes): bf16 rows padded to 36 elements (72 B)
#define RS 72
#define AH_OFF 0
#define AL_OFF (128 * RS)
#define BH_OFF (2 * 128 * RS)
#define BL_OFF (BH_OFF + 64 * RS)
#define PROJ_SMEM (BL_OFF + 64 * RS)

// ---------------------------------------------------------------------------
// Tensor-core proj GEMM via mma.sync bf16x3 (unchanged from round 7).
// ---------------------------------------------------------------------------
__global__ __launch_bounds__(128) void proj_mma(
        const float* __restrict__ queries, const float* __restrict__ keys,
        const float* __restrict__ Wq, const float* __restrict__ Wk,
        const int* __restrict__ vlens) {
    extern __shared__ __align__(16) char sm[];
    const int tid = threadIdx.x, lane = tid & 31, w = tid >> 5;
    const int row0 = blockIdx.y * 128, bn = blockIdx.x * 64;

    const float *Ap, *Wp;
    float* Cp;
    if (row0 < Bb * Qq) {
        Ap = queries + (long)row0 * Dd; Wp = Wq; Cp = g_qh + (long)row0 * Hh;
    } else {
        const int krow = row0 - Bb * Qq;
        const int b    = krow >> 9;
        if ((krow & (KK - 1)) >= vlens[b]) return;   // fully-masked key tile
        Ap = keys + (long)krow * Dd; Wp = Wk; Cp = g_kh + (long)krow * Hh;
    }

    const int gr = lane >> 2;
    const int c2 = (lane & 3) << 1;

    float acc[2][8][4] = {};

    float4 ra[8], rw[4];
    #pragma unroll
    for (int r = 0; r < 8; r++) {
        int i = tid + 128 * r;
        ra[r] = *(const float4*)(Ap + (long)(i >> 3) * Dd + ((i & 7) << 2));
    }
    #pragma unroll
    for (int r = 0; r < 4; r++) {
        int i = tid + 128 * r;
        rw[r] = *(const float4*)(Wp + (long)(i >> 4) * Hh + bn + ((i & 15) << 2));
    }

    const int NS = Dd / KS;    // 16 slices
    for (int s = 0; s < NS; s++) {
        #pragma unroll
        for (int r = 0; r < 8; r++) {
            int i = tid + 128 * r;
            int row = i >> 3, kc = (i & 7) << 2;
            uint32_t h0, l0, h1, l1;
            cvt_split2(ra[r].x, ra[r].y, h0, l0);
            cvt_split2(ra[r].z, ra[r].w, h1, l1);
            *(uint2*)(sm + AH_OFF + row * RS + kc * 2) = make_uint2(h0, h1);
            *(uint2*)(sm + AL_OFF + row * RS + kc * 2) = make_uint2(l0, l1);
        }
        #pragma unroll
        for (int r = 0; r < 4; r++) {
            int i = tid + 128 * r;
            int k = i >> 4, nc = (i & 15) << 2;
            float v[4] = {rw[r].x, rw[r].y, rw[r].z, rw[r].w};
            #pragma unroll
            for (int j = 0; j < 4; j++) {
                uint16_t hh, ll;
                split1(v[j], hh, ll);
                *(uint16_t*)(sm + BH_OFF + (nc + j) * RS + k * 2) = hh;
                *(uint16_t*)(sm + BL_OFF + (nc + j) * RS + k * 2) = ll;
            }
        }
        __syncthreads();

        if (s + 1 < NS) {
            const float* Ab = Ap + (s + 1) * KS;
            const float* Wb = Wp + (long)(s + 1) * KS * Hh;
            #pragma unroll
            for (int r = 0; r < 8; r++) {
                int i = tid + 128 * r;
                ra[r] = *(const float4*)(Ab + (long)(i >> 3) * Dd + ((i & 7) << 2));
            }
            #pragma unroll
            for (int r = 0; r < 4; r++) {
                int i = tid + 128 * r;
                rw[r] = *(const float4*)(Wb + (long)(i >> 4) * Hh + bn + ((i & 15) << 2));
            }
        }

        #pragma unroll
        for (int kh = 0; kh < 2; kh++) {
            const int kb = kh * 16;
            uint32_t ah[2][4], al[2][4];
            #pragma unroll
            for (int t = 0; t < 2; t++) {
                const int mr = w * 32 + 16 * t + gr;
                const char* pA = sm + (long)mr * RS + (kb + c2) * 2;
                ah[t][0] = *(const uint32_t*)(pA + AH_OFF);
                ah[t][1] = *(const uint32_t*)(pA + AH_OFF + 8 * RS);
                ah[t][2] = *(const uint32_t*)(pA + AH_OFF + 16);
                ah[t][3] = *(const uint32_t*)(pA + AH_OFF + 8 * RS + 16);
                al[t][0] = *(const uint32_t*)(pA + AL_OFF);
                al[t][1] = *(const uint32_t*)(pA + AL_OFF + 8 * RS);
                al[t][2] = *(const uint32_t*)(pA + AL_OFF + 16);
                al[t][3] = *(const uint32_t*)(pA + AL_OFF + 8 * RS + 16);
            }
            #pragma unroll
            for (int j = 0; j < 8; j++) {
                const int nr = 8 * j + gr;
                const char* pB = sm + (long)nr * RS + (kb + c2) * 2;
                uint32_t bh0 = *(const uint32_t*)(pB + BH_OFF);
                uint32_t bh1 = *(const uint32_t*)(pB + BH_OFF + 16);
                uint32_t bl0 = *(const uint32_t*)(pB + BL_OFF);
                uint32_t bl1 = *(const uint32_t*)(pB + BL_OFF + 16);
                #pragma unroll
                for (int t = 0; t < 2; t++) {
                    MMA_BF16(acc[t][j], ah[t], bh0, bh1);
                    MMA_BF16(acc[t][j], ah[t], bl0, bl1);
                    MMA_BF16(acc[t][j], al[t], bh0, bh1);
                }
            }
        }
        __syncthreads();
    }

    #pragma unroll
    for (int t = 0; t < 2; t++) {
        const int mr = w * 32 + 16 * t + gr;
        #pragma unroll
        for (int j = 0; j < 8; j++) {
            float* cp = Cp + (long)mr * Hh + bn + 8 * j + c2;
            *(float2*)cp            = make_float2(acc[t][j][0], acc[t][j][1]);
            *(float2*)(cp + 8 * Hh) = make_float2(acc[t][j][2], acc[t][j][3]);
        }
    }
}

// ---------------------------------------------------------------------------
// S1: balanced scoring pass (unchanged from round 8).
// ---------------------------------------------------------------------------
#define S1_QT 65
#define S1_KT 18
#define S1_SMEM (Hh * S1_QT * 4 + Hh * S1_KT * 4)

__global__ __launch_bounds__(256) void score_pass(
        const float* __restrict__ Wv, const int* __restrict__ vlens) {
    const int kt = blockIdx.x;
    const int b  = blockIdx.y;
    const int vl = vlens[b];
    if (kt * 16 >= vl) return;

    extern __shared__ float s1[];
    float* qt = s1;                        // [256][65]
    float* ktl = s1 + Hh * S1_QT;          // [256][18], [h][16] = Wv[h]

    const int tid  = threadIdx.x;
    const int lane = tid & 31;
    const int w    = tid >> 5;

    {
        const float4* src = (const float4*)(g_qh + (long)b * Qq * Hh);
        #pragma unroll
        for (int r = 0; r < 16; r++) {
            int i = tid + 256 * r;
            int q = i >> 6, h0 = (i & 63) << 2;
            float4 v = src[i];
            qt[(h0 + 0) * S1_QT + q] = v.x;
            qt[(h0 + 1) * S1_QT + q] = v.y;
            qt[(h0 + 2) * S1_QT + q] = v.z;
            qt[(h0 + 3) * S1_QT + q] = v.w;
        }
    }
    {
        const float4* src = (const float4*)(g_kh + ((long)b * KK + kt * 16) * Hh);
        #pragma unroll
        for (int r = 0; r < 4; r++) {
            int i = tid + 256 * r;
            int k = i >> 6, h0 = (i & 63) << 2;
            float4 v = src[i];
            ktl[(h0 + 0) * S1_KT + k] = v.x;
            ktl[(h0 + 1) * S1_KT + k] = v.y;
            ktl[(h0 + 2) * S1_KT + k] = v.z;
            ktl[(h0 + 3) * S1_KT + k] = v.w;
        }
    }
    ktl[tid * S1_KT + 16] = Wv[tid];
    __syncthreads();

    float a00 = 0.f, a01 = 0.f, a10 = 0.f, a11 = 0.f;
    #pragma unroll 4
    for (int h = 0; h < Hh; h++) {
        const float* kr = ktl + h * S1_KT;
        float2 kv = *(const float2*)(kr + 2 * w);
        float  wv = kr[16];
        float  qa = qt[h * S1_QT + lane];
        float  qb = qt[h * S1_QT + lane + 32];
        a00 = fmaf(wv, tanhx(qa + kv.x), a00);
        a01 = fmaf(wv, tanhx(qa + kv.y), a01);
        a10 = fmaf(wv, tanhx(qb + kv.x), a10);
        a11 = fmaf(wv, tanhx(qb + kv.y), a11);
    }

    float* d0 = g_attn + ((long)b * Qq + lane) * KK + kt * 16 + 2 * w;
    *(float2*)d0              = make_float2(a00, a01);
    *(float2*)(d0 + 32 * KK)  = make_float2(a10, a11);
}

// ---------------------------------------------------------------------------
// S2: masked softmax over g_attn rows, in place (unchanged).
// ---------------------------------------------------------------------------
__global__ __launch_bounds__(128) void softmax_k(const int* __restrict__ vlens) {
    const int b    = blockIdx.x >> 4;
    const int q0   = (blockIdx.x & 15) * 4;
    const int lane = threadIdx.x & 31;
    const int w    = threadIdx.x >> 5;
    const int vl   = vlens[b];

    float* row = g_attn + ((long)b * Qq + q0 + w) * KK;

    float vals[16];
    float mx = -3.0e38f;
    #pragma unroll
    for (int i = 0; i < 16; i++) {
        int k = 32 * i + lane;
        float v = (k < vl) ? row[k] : -1e6f;
        vals[i] = v;
        mx = fmaxf(mx, v);
    }
    #pragma unroll
    for (int off = 16; off; off >>= 1)
        mx = fmaxf(mx, __shfl_xor_sync(0xffffffffu, mx, off));
    float sum = 0.f;
    #pragma unroll
    for (int i = 0; i < 16; i++) {
        float e = __expf(vals[i] - mx);   // masked -> exactly 0
        vals[i] = e;
        sum += e;
    }
    #pragma unroll
    for (int off = 16; off; off >>= 1)
        sum += __shfl_xor_sync(0xffffffffu, sum, off);
    const float inv = __fdividef(1.f, sum);
    #pragma unroll
    for (int i = 0; i < 16; i++)
        row[32 * i + lane] = vals[i] * inv;
}

// ---------------------------------------------------------------------------
// Tensor-core AV GEMM: out[b] = attn[b] (64xK) @ values[b] (KxDd),
// K bounded at align32(vl) (attn exactly 0 beyond vl after S2).
// CTA = 64x64 tile, 128 threads / 4 warps, warp = 16(M) x 64(N).
// bf16x3 split product, K staged 32-wide in hi/lo smem (72B-padded rows).
// grid = (Dd/64 = 8, Bb), block = 128.
// ---------------------------------------------------------------------------
#define AV_AH 0
#define AV_AL (64 * RS)
#define AV_BH (2 * 64 * RS)
#define AV_BL (AV_BH + 64 * RS)
#define AV_SMEM (AV_BL + 64 * RS)

__global__ __launch_bounds__(128) void av_mma(
        const float* __restrict__ values, float* __restrict__ out,
        const int* __restrict__ vlens) {
    extern __shared__ __align__(16) char sma[];
    const int tid = threadIdx.x, lane = tid & 31, w = tid >> 5;
    const int b = blockIdx.y, bn = blockIdx.x * 64;

    const float* Ap = g_attn + (long)b * Qq * KK;
    const float* Bp = values + (long)b * KK * Dd;
    float* Cp       = out + (long)b * Qq * Dd;
    const int nsl   = (((vlens[b] + 31) & ~31) >> 5);   // 1..16 K-slices of 32

    const int gr = lane >> 2;
    const int c2 = (lane & 3) << 1;

    float acc[8][4] = {};

    float4 ra[4], rw[4];
    // prologue LDG slice 0: A 64x32 (4 f4/thr), B 32x64 (4 f4/thr)
    #pragma unroll
    for (int r = 0; r < 4; r++) {
        int i = tid + 128 * r;
        ra[r] = *(const float4*)(Ap + (long)(i >> 3) * KK + ((i & 7) << 2));
    }
    #pragma unroll
    for (int r = 0; r < 4; r++) {
        int i = tid + 128 * r;
        rw[r] = *(const float4*)(Bp + (long)(i >> 4) * Dd + bn + ((i & 15) << 2));
    }

    for (int s = 0; s < nsl; s++) {
        // STS A (attn) hi/lo
        #pragma unroll
        for (int r = 0; r < 4; r++) {
            int i = tid + 128 * r;
            int row = i >> 3, kc = (i & 7) << 2;
            uint32_t h0, l0, h1, l1;
            cvt_split2(ra[r].x, ra[r].y, h0, l0);
            cvt_split2(ra[r].z, ra[r].w, h1, l1);
            *(uint2*)(sma + AV_AH + row * RS + kc * 2) = make_uint2(h0, h1);
            *(uint2*)(sma + AV_AL + row * RS + kc * 2) = make_uint2(l0, l1);
        }
        // STS B (values) transposed to [n][k]
        #pragma unroll
        for (int r = 0; r < 4; r++) {
            int i = tid + 128 * r;
            int k = i >> 4, nc = (i & 15) << 2;
            float v[4] = {rw[r].x, rw[r].y, rw[r].z, rw[r].w};
            #pragma unroll
            for (int j = 0; j < 4; j++) {
                uint16_t hh, ll;
                split1(v[j], hh, ll);
                *(uint16_t*)(sma + AV_BH + (nc + j) * RS + k * 2) = hh;
                *(uint16_t*)(sma + AV_BL + (nc + j) * RS + k * 2) = ll;
            }
        }
        __syncthreads();

        // prefetch slice s+1
        if (s + 1 < nsl) {
            const float* Ab = Ap + (s + 1) * 32;
            const float* Bb2 = Bp + (long)(s + 1) * 32 * Dd;
            #pragma unroll
            for (int r = 0; r < 4; r++) {
                int i = tid + 128 * r;
                ra[r] = *(const float4*)(Ab + (long)(i >> 3) * KK + ((i & 7) << 2));
            }
            #pragma unroll
            for (int r = 0; r < 4; r++) {
                int i = tid + 128 * r;
                rw[r] = *(const float4*)(Bb2 + (long)(i >> 4) * Dd + bn + ((i & 15) << 2));
            }
        }

        // compute: 2 k16 halves x 8 n-tiles x 3 split products
        #pragma unroll
        for (int kh = 0; kh < 2; kh++) {
            const int kb = kh * 16;
            uint32_t ah[4], al[4];
            const int mr = w * 16 + gr;
            const char* pA = sma + (long)mr * RS + (kb + c2) * 2;
            ah[0] = *(const uint32_t*)(pA + AV_AH);
            ah[1] = *(const uint32_t*)(pA + AV_AH + 8 * RS);
            ah[2] = *(const uint32_t*)(pA + AV_AH + 16);
            ah[3] = *(const uint32_t*)(pA + AV_AH + 8 * RS + 16);
            al[0] = *(const uint32_t*)(pA + AV_AL);
            al[1] = *(const uint32_t*)(pA + AV_AL + 8 * RS);
            al[2] = *(const uint32_t*)(pA + AV_AL + 16);
            al[3] = *(const uint32_t*)(pA + AV_AL + 8 * RS + 16);
            #pragma unroll
            for (int j = 0; j < 8; j++) {
                const int nr = 8 * j + gr;
                const char* pB = sma + (long)nr * RS + (kb + c2) * 2;
                uint32_t bh0 = *(const uint32_t*)(pB + AV_BH);
                uint32_t bh1 = *(const uint32_t*)(pB + AV_BH + 16);
                uint32_t bl0 = *(const uint32_t*)(pB + AV_BL);
                uint32_t bl1 = *(const uint32_t*)(pB + AV_BL + 16);
                MMA_BF16(acc[j], ah, bh0, bh1);
                MMA_BF16(acc[j], ah, bl0, bl1);
                MMA_BF16(acc[j], al, bh0, bh1);
            }
        }
        __syncthreads();
    }

    // epilogue: warp rows gr, gr+8 within its 16-row band
    {
        const int mr = w * 16 + gr;
        #pragma unroll
        for (int j = 0; j < 8; j++) {
            float* cp = Cp + (long)mr * Dd + bn + 8 * j + c2;
            *(float2*)cp            = make_float2(acc[j][0], acc[j][1]);
            *(float2*)(cp + 8 * Dd) = make_float2(acc[j][2], acc[j][3]);
        }
    }
}

extern "C" void kernel_launch(void* const* d_in, const int* in_sizes, int n_in,
                              void* d_out, int out_size) {
    const float* queries = (const float*)d_in[0];  // [16,64,512]
    const float* keys    = (const float*)d_in[1];  // [16,512,512]
    const float* values  = (const float*)d_in[2];  // [16,512,512]
    const int*   vlens   = (const int*)d_in[3];    // [16]
    const float* Wq      = (const float*)d_in[4];  // [512,256]
    const float* Wk      = (const float*)d_in[5];  // [512,256]
    const float* Wv      = (const float*)d_in[6];  // [256]
    float* out = (float*)d_out;                    // [16,64,512]

    cudaFuncSetAttribute(proj_mma,
                         cudaFuncAttributeMaxDynamicSharedMemorySize, PROJ_SMEM);
    cudaFuncSetAttribute(score_pass,
                         cudaFuncAttributeMaxDynamicSharedMemorySize, S1_SMEM);
    cudaFuncSetAttribute(av_mma,
                         cudaFuncAttributeMaxDynamicSharedMemorySize, AV_SMEM);

    proj_mma<<<dim3(Hh / 64, (Bb * Qq + Bb * KK) / 128), 128, PROJ_SMEM>>>(
        queries, keys, Wq, Wk, vlens);
    score_pass<<<dim3(KK / 16, Bb), 256, S1_SMEM>>>(Wv, vlens);
    softmax_k<<<Bb * 16, 128>>>(vlens);
    av_mma<<<dim3(Dd / 64, Bb), 128, AV_SMEM>>>(values, out, vlens);
}